// round 7
// baseline (speedup 1.0000x reference)
#include <cuda_runtime.h>

// ---------------- problem constants ----------------
#define NB   32
#define SEQ  1024
#define NF   512
#define NCH  38      // grid 32*38 = 1216 = 8 blocks/SM exactly
#define CLEN 27      // chunks 0..36 have 27 steps, chunk 37 has 25
#define MU_C 10.0f
#define LOGLIK2 (-3947.8417604357434f)   // -MU*T*(2*pi)^(D-1)
#define MLP_G 8      // fourier samples per mlp block

typedef unsigned long long ull;

// ---------------- scratch (__device__ globals: no allocation) ----------------
__device__ float g_womg[3 * NF];          // Womg[d][n]
__device__ ull   g_sums[NB * NCH * NF];   // packed (sumC, sumS); after scan: exclusive base

// ---------------- f32x2 packed helpers (sm_103a) ----------------
static __device__ __forceinline__ ull pk2(float lo, float hi) {
    ull r; asm("mov.b64 %0, {%1, %2};" : "=l"(r) : "f"(lo), "f"(hi)); return r;
}
static __device__ __forceinline__ void up2(ull v, float& lo, float& hi) {
    asm("mov.b64 {%0, %1}, %2;" : "=f"(lo), "=f"(hi) : "l"(v));
}
static __device__ __forceinline__ ull fma2(ull a, ull b, ull c) {
    ull r; asm("fma.rn.f32x2 %0, %1, %2, %3;" : "=l"(r) : "l"(a), "l"(b), "l"(c)); return r;
}
static __device__ __forceinline__ ull mul2(ull a, ull b) {
    ull r; asm("mul.rn.f32x2 %0, %1, %2;" : "=l"(r) : "l"(a), "l"(b)); return r;
}
static __device__ __forceinline__ ull add2(ull a, ull b) {
    ull r; asm("add.rn.f32x2 %0, %1, %2;" : "=l"(r) : "l"(a), "l"(b)); return r;
}
static __device__ __forceinline__ float fsin(float x) {
    float r; asm("sin.approx.f32 %0, %1;" : "=f"(r) : "f"(x)); return r;
}
static __device__ __forceinline__ float fcos(float x) {
    float r; asm("cos.approx.f32 %0, %1;" : "=f"(r) : "f"(x)); return r;
}
static __device__ __forceinline__ float warp_sum(float x) {
#pragma unroll
    for (int o = 16; o > 0; o >>= 1) x += __shfl_xor_sync(0xffffffffu, x, o);
    return x;
}

// ---------------- Kernel A: fourier MLP -> Womg[3][512] ----------------
// 64 blocks x 256 threads, 8 samples/block. W1 staged in smem; W2 streamed
// ONCE per block with 8-way reuse (was: 512 blocks each re-reading 128KB).
__global__ void __launch_bounds__(256) mlp_womg(
    const float* __restrict__ noise, const float* __restrict__ W1,
    const float* __restrict__ b1, const float* __restrict__ W2,
    const float* __restrict__ b2, const float* __restrict__ Wm)
{
    __shared__ float sW1[64 * 100];       // 25.6 KB
    __shared__ float sn[MLP_G][64];
    __shared__ float sh[MLP_G][100];
    __shared__ float sacc[MLP_G][3];
    const int t = threadIdx.x;
    const int n0 = blockIdx.x * MLP_G;

    for (int i = t; i < 64 * 100; i += 256) sW1[i] = W1[i];
    for (int i = t; i < MLP_G * 64; i += 256) sn[i >> 6][i & 63] = noise[n0 * 64 + i];
    if (t < MLP_G * 3) sacc[t / 3][t % 3] = 0.f;
    __syncthreads();

    // hidden layer: MLP_G*100 = 800 dot products of length 64
    for (int idx = t; idx < MLP_G * 100; idx += 256) {
        const int s = idx / 100, h = idx - s * 100;
        float a = b1[h];
#pragma unroll 8
        for (int k = 0; k < 64; k++) a += sn[s][k] * sW1[k * 100 + h];
        sh[s][h] = tanhf(a);
    }
    __syncthreads();

    // output layer: thread owns feature column f = t; 8 samples in registers
    float acc[MLP_G];
    const float bb = b2[t];
#pragma unroll
    for (int s = 0; s < MLP_G; s++) acc[s] = bb;
#pragma unroll 2
    for (int h = 0; h < 100; h++) {
        const float w = W2[h * 256 + t];
#pragma unroll
        for (int s = 0; s < MLP_G; s++) acc[s] += sh[s][h] * w;
    }
    const float wm0 = Wm[t * 3 + 0], wm1 = Wm[t * 3 + 1], wm2 = Wm[t * 3 + 2];
#pragma unroll
    for (int s = 0; s < MLP_G; s++) {
        const float f = tanhf(acc[s]);
        const float p0 = warp_sum(f * wm0);
        const float p1 = warp_sum(f * wm1);
        const float p2 = warp_sum(f * wm2);
        if ((t & 31) == 0) {
            atomicAdd(&sacc[s][0], p0);
            atomicAdd(&sacc[s][1], p1);
            atomicAdd(&sacc[s][2], p2);
        }
    }
    __syncthreads();
    if (t < MLP_G * 3) {
        const int s = t / 3, d = t - s * 3;
        g_womg[d * NF + n0 + s] = sacc[s][d];
    }
}

// ---------------- Kernel B: per-chunk (sumC, sumS) ----------------
// grid NB*NCH = 1216, 256 threads, thread owns n in {t, t+256}
__global__ void __launch_bounds__(256, 8) chunk_sums(const float* __restrict__ X)
{
    __shared__ float4 sx[CLEN];
    const int bx = blockIdx.x;
    const int b = bx / NCH;
    const int ch = bx - b * NCH;
    const int i0 = ch * CLEN;
    const int clen = (ch == NCH - 1) ? (SEQ - i0) : CLEN;
    const int t = threadIdx.x;

    if (t < clen) {
        const float* xp = X + (size_t)(b * SEQ + i0 + t) * 3;
        sx[t] = make_float4(xp[0], xp[1], xp[2], 0.f);
    }
    const ull w0 = pk2(g_womg[0 * NF + t], g_womg[0 * NF + t + 256]);
    const ull w1 = pk2(g_womg[1 * NF + t], g_womg[1 * NF + t + 256]);
    const ull w2 = pk2(g_womg[2 * NF + t], g_womg[2 * NF + t + 256]);
    __syncthreads();

    ull cA = 0ull, cC = 0ull;
#pragma unroll 4
    for (int i = 0; i < clen; i++) {
        const float4 x = sx[i];
        const ull x0 = pk2(x.x, x.x), x1 = pk2(x.y, x.y), x2 = pk2(x.z, x.z);
        const ull th = fma2(x2, w2, fma2(x1, w1, mul2(x0, w0)));
        float tA, tC;
        up2(th, tA, tC);
        cA = add2(cA, pk2(fcos(tA), fsin(tA)));
        cC = add2(cC, pk2(fcos(tC), fsin(tC)));
    }
    ull* o = g_sums + (size_t)(b * NCH + ch) * NF;
    o[t]       = cA;
    o[t + 256] = cC;
}

// ---------------- Kernel C: exclusive scan over chunks + loglik tail ----------------
// grid NB*4 = 128 blocks x 128 threads: block (b, quarter of n-range)
__global__ void __launch_bounds__(128) scan_sums(float* __restrict__ out)
{
    const int b = blockIdx.x >> 2;
    const int q = blockIdx.x & 3;
    const int n = q * 128 + threadIdx.x;
    ull v[NCH];
    ull* base = g_sums + (size_t)b * NCH * NF + n;
#pragma unroll
    for (int c = 0; c < NCH; c++) v[c] = base[(size_t)c * NF];
    ull run = 0ull;
#pragma unroll
    for (int c = 0; c < NCH; c++) {
        base[(size_t)c * NF] = run;
        run = add2(run, v[c]);
    }
    if (n == 0) out[NB * SEQ + b * (SEQ + 1) + SEQ] = LOGLIK2;
}

// ---------------- Kernel D: contraction + outputs ----------------
// grid NB*NCH = 1216, 256 threads; STS-deferred reduction (round-5 body, fastest)
__global__ void __launch_bounds__(256, 8) main_contract(
    const float* __restrict__ X,
    const float* __restrict__ alpha,
    float* __restrict__ out)
{
    __shared__ float4 sx[CLEN];
    __shared__ float ctr[CLEN * 256];   // 27 KB per-thread contribs, deferred reduce
    const int bx = blockIdx.x;
    const int b = bx / NCH;
    const int ch = bx - b * NCH;
    const int i0 = ch * CLEN;
    const int clen = (ch == NCH - 1) ? (SEQ - i0) : CLEN;
    const int t = threadIdx.x;
    const int w = t >> 5;
    const int l = t & 31;

    if (t < clen) {
        const float* xp = X + (size_t)(b * SEQ + i0 + t) * 3;
        sx[t] = make_float4(xp[0], xp[1], xp[2], 0.f);
    }
    const ull w0 = pk2(g_womg[0 * NF + t], g_womg[0 * NF + t + 256]);
    const ull w1 = pk2(g_womg[1 * NF + t], g_womg[1 * NF + t + 256]);
    const ull w2 = pk2(g_womg[2 * NF + t], g_womg[2 * NF + t + 256]);

    const ull* basep = g_sums + (size_t)(b * NCH + ch) * NF;
    ull cumA = basep[t];
    ull cumC = basep[t + 256];
    __syncthreads();

#pragma unroll 4
    for (int i = 0; i < clen; i++) {
        const float4 x = sx[i];
        const ull x0 = pk2(x.x, x.x), x1 = pk2(x.y, x.y), x2 = pk2(x.z, x.z);
        const ull th = fma2(x2, w2, fma2(x1, w1, mul2(x0, w0)));
        float tA, tC;
        up2(th, tA, tC);
        const ull csA = pk2(fcos(tA), fsin(tA));
        const ull csC = pk2(fcos(tC), fsin(tC));
        const ull pA = mul2(csA, cumA); cumA = add2(cumA, csA);
        const ull pC = mul2(csC, cumC); cumC = add2(cumC, csC);
        const ull s = add2(pA, pC);
        float lo, hi;
        up2(s, lo, hi);
        ctr[i * 256 + t] = lo + hi;
    }
    __syncthreads();

    const float alph = alpha[0];
    for (int i = w; i < clen; i += 8) {
        float v = 0.f;
#pragma unroll
        for (int k = 0; k < 8; k++) v += ctr[i * 256 + l + k * 32];
        v = warp_sum(v);
        if (l == 0) {
            const float lam = alph * (v * (1.0f / (float)NF)) + MU_C;
            const int gi = i0 + i;
            out[b * SEQ + gi] = lam;
            const float x0 = sx[i].x;
            out[NB * SEQ + b * (SEQ + 1) + gi] = (x0 > 0.f ? logf(lam) : 0.f) + LOGLIK2;
        }
    }
}

// ---------------- launch ----------------
extern "C" void kernel_launch(void* const* d_in, const int* in_sizes, int n_in,
                              void* d_out, int out_size)
{
    const float* X     = (const float*)d_in[0];
    const float* noise = (const float*)d_in[1];
    const float* W1    = (const float*)d_in[2];
    const float* b1    = (const float*)d_in[3];
    const float* W2    = (const float*)d_in[4];
    const float* b2    = (const float*)d_in[5];
    const float* Wm    = (const float*)d_in[6];
    const float* alpha = (const float*)d_in[7];
    float* out = (float*)d_out;

    mlp_womg<<<NF / MLP_G, 256>>>(noise, W1, b1, W2, b2, Wm);
    chunk_sums<<<NB * NCH, 256>>>(X);
    scan_sums<<<NB * 4, 128>>>(out);
    main_contract<<<NB * NCH, 256>>>(X, alpha, out);
}

// round 10
// speedup vs baseline: 1.1885x; 1.1885x over previous
#include <cuda_runtime.h>

// ---------------- problem constants ----------------
#define NB   32
#define SEQ  1024
#define NF   512
#define NCH  38      // grid 32*38 = 1216 = 8 blocks/SM exactly
#define CLEN 27      // chunks 0..36 have 27 steps, chunk 37 has 25
#define MU_C 10.0f
#define LOGLIK2 (-3947.8417604357434f)   // -MU*T*(2*pi)^(D-1)

typedef unsigned long long ull;

// ---------------- scratch (__device__ globals: no allocation) ----------------
__device__ float g_womg[3 * NF];          // Womg[d][n]
__device__ ull   g_sums[NB * NCH * NF];   // packed (sumC, sumS); after scan: exclusive base

// ---------------- f32x2 packed helpers (sm_103a) ----------------
static __device__ __forceinline__ ull pk2(float lo, float hi) {
    ull r; asm("mov.b64 %0, {%1, %2};" : "=l"(r) : "f"(lo), "f"(hi)); return r;
}
static __device__ __forceinline__ void up2(ull v, float& lo, float& hi) {
    asm("mov.b64 {%0, %1}, %2;" : "=f"(lo), "=f"(hi) : "l"(v));
}
static __device__ __forceinline__ ull fma2(ull a, ull b, ull c) {
    ull r; asm("fma.rn.f32x2 %0, %1, %2, %3;" : "=l"(r) : "l"(a), "l"(b), "l"(c)); return r;
}
static __device__ __forceinline__ ull mul2(ull a, ull b) {
    ull r; asm("mul.rn.f32x2 %0, %1, %2;" : "=l"(r) : "l"(a), "l"(b)); return r;
}
static __device__ __forceinline__ ull add2(ull a, ull b) {
    ull r; asm("add.rn.f32x2 %0, %1, %2;" : "=l"(r) : "l"(a), "l"(b)); return r;
}
static __device__ __forceinline__ float fsin(float x) {
    float r; asm("sin.approx.f32 %0, %1;" : "=f"(r) : "f"(x)); return r;
}
static __device__ __forceinline__ float fcos(float x) {
    float r; asm("cos.approx.f32 %0, %1;" : "=f"(r) : "f"(x)); return r;
}
static __device__ __forceinline__ float warp_sum(float x) {
#pragma unroll
    for (int o = 16; o > 0; o >>= 1) x += __shfl_xor_sync(0xffffffffu, x, o);
    return x;
}

// ---------------- Kernel A: fourier MLP -> Womg[3][512] ----------------
// R2 version: 512 blocks x 128 threads — spreads over all SMs; W1/W2 are L2-resident.
__global__ void __launch_bounds__(128) mlp_womg(
    const float* __restrict__ noise, const float* __restrict__ W1,
    const float* __restrict__ b1, const float* __restrict__ W2,
    const float* __restrict__ b2, const float* __restrict__ Wm)
{
    __shared__ float sn[64];
    __shared__ float sh[100];
    __shared__ float wp[4][3];
    const int n = blockIdx.x;
    const int t = threadIdx.x;

    if (t < 64) sn[t] = noise[n * 64 + t];
    __syncthreads();

    if (t < 100) {
        float a = b1[t];
#pragma unroll 8
        for (int k = 0; k < 64; k++) a += sn[k] * W1[k * 100 + t];
        sh[t] = tanhf(a);
    }
    __syncthreads();

    float a0 = b2[t], a1 = b2[t + 128];
#pragma unroll 4
    for (int h = 0; h < 100; h++) {
        const float hv = sh[h];
        a0 += hv * W2[h * 256 + t];
        a1 += hv * W2[h * 256 + t + 128];
    }
    const float f0 = tanhf(a0);
    const float f1 = tanhf(a1);

    float pd0 = warp_sum(f0 * Wm[t * 3 + 0] + f1 * Wm[(t + 128) * 3 + 0]);
    float pd1 = warp_sum(f0 * Wm[t * 3 + 1] + f1 * Wm[(t + 128) * 3 + 1]);
    float pd2 = warp_sum(f0 * Wm[t * 3 + 2] + f1 * Wm[(t + 128) * 3 + 2]);
    if ((t & 31) == 0) { wp[t >> 5][0] = pd0; wp[t >> 5][1] = pd1; wp[t >> 5][2] = pd2; }
    __syncthreads();
    if (t == 0) {
#pragma unroll
        for (int d = 0; d < 3; d++)
            g_womg[d * NF + n] = wp[0][d] + wp[1][d] + wp[2][d] + wp[3][d];
    }
}

// ---------------- Kernel B: per-chunk (sumC, sumS) ----------------
// grid NB*NCH = 1216, 256 threads, thread owns n in {t, t+256}
__global__ void __launch_bounds__(256, 8) chunk_sums(const float* __restrict__ X)
{
    __shared__ float4 sx[CLEN];
    const int bx = blockIdx.x;
    const int b = bx / NCH;
    const int ch = bx - b * NCH;
    const int i0 = ch * CLEN;
    const int clen = (ch == NCH - 1) ? (SEQ - i0) : CLEN;
    const int t = threadIdx.x;

    if (t < clen) {
        const float* xp = X + (size_t)(b * SEQ + i0 + t) * 3;
        sx[t] = make_float4(xp[0], xp[1], xp[2], 0.f);
    }
    const ull w0 = pk2(g_womg[0 * NF + t], g_womg[0 * NF + t + 256]);
    const ull w1 = pk2(g_womg[1 * NF + t], g_womg[1 * NF + t + 256]);
    const ull w2 = pk2(g_womg[2 * NF + t], g_womg[2 * NF + t + 256]);
    __syncthreads();

    ull cA = 0ull, cC = 0ull;
#pragma unroll 4
    for (int i = 0; i < clen; i++) {
        const float4 x = sx[i];
        const ull x0 = pk2(x.x, x.x), x1 = pk2(x.y, x.y), x2 = pk2(x.z, x.z);
        const ull th = fma2(x2, w2, fma2(x1, w1, mul2(x0, w0)));
        float tA, tC;
        up2(th, tA, tC);
        cA = add2(cA, pk2(fcos(tA), fsin(tA)));
        cC = add2(cC, pk2(fcos(tC), fsin(tC)));
    }
    ull* o = g_sums + (size_t)(b * NCH + ch) * NF;
    o[t]       = cA;
    o[t + 256] = cC;
}

// ---------------- Kernel C: exclusive scan over chunks + loglik tail ----------------
// grid NB*4 = 128 blocks x 128 threads: block (b, quarter of n-range)
__global__ void __launch_bounds__(128) scan_sums(float* __restrict__ out)
{
    const int b = blockIdx.x >> 2;
    const int q = blockIdx.x & 3;
    const int n = q * 128 + threadIdx.x;
    ull v[NCH];
    ull* base = g_sums + (size_t)b * NCH * NF + n;
#pragma unroll
    for (int c = 0; c < NCH; c++) v[c] = base[(size_t)c * NF];
    ull run = 0ull;
#pragma unroll
    for (int c = 0; c < NCH; c++) {
        base[(size_t)c * NF] = run;
        run = add2(run, v[c]);
    }
    if (n == 0) out[NB * SEQ + b * (SEQ + 1) + SEQ] = LOGLIK2;
}

// ---------------- Kernel D: contraction + outputs ----------------
// grid NB*NCH = 1216, 256 threads; STS-deferred reduction (best measured: 14.05us)
__global__ void __launch_bounds__(256, 8) main_contract(
    const float* __restrict__ X,
    const float* __restrict__ alpha,
    float* __restrict__ out)
{
    __shared__ float4 sx[CLEN];
    __shared__ float ctr[CLEN * 256];   // 27 KB per-thread contribs, deferred reduce
    const int bx = blockIdx.x;
    const int b = bx / NCH;
    const int ch = bx - b * NCH;
    const int i0 = ch * CLEN;
    const int clen = (ch == NCH - 1) ? (SEQ - i0) : CLEN;
    const int t = threadIdx.x;
    const int w = t >> 5;
    const int l = t & 31;

    if (t < clen) {
        const float* xp = X + (size_t)(b * SEQ + i0 + t) * 3;
        sx[t] = make_float4(xp[0], xp[1], xp[2], 0.f);
    }
    const ull w0 = pk2(g_womg[0 * NF + t], g_womg[0 * NF + t + 256]);
    const ull w1 = pk2(g_womg[1 * NF + t], g_womg[1 * NF + t + 256]);
    const ull w2 = pk2(g_womg[2 * NF + t], g_womg[2 * NF + t + 256]);

    const ull* basep = g_sums + (size_t)(b * NCH + ch) * NF;
    ull cumA = basep[t];
    ull cumC = basep[t + 256];
    __syncthreads();

#pragma unroll 4
    for (int i = 0; i < clen; i++) {
        const float4 x = sx[i];
        const ull x0 = pk2(x.x, x.x), x1 = pk2(x.y, x.y), x2 = pk2(x.z, x.z);
        const ull th = fma2(x2, w2, fma2(x1, w1, mul2(x0, w0)));
        float tA, tC;
        up2(th, tA, tC);
        const ull csA = pk2(fcos(tA), fsin(tA));
        const ull csC = pk2(fcos(tC), fsin(tC));
        const ull pA = mul2(csA, cumA); cumA = add2(cumA, csA);
        const ull pC = mul2(csC, cumC); cumC = add2(cumC, csC);
        const ull s = add2(pA, pC);
        float lo, hi;
        up2(s, lo, hi);
        ctr[i * 256 + t] = lo + hi;
    }
    __syncthreads();

    const float alph = alpha[0];
    for (int i = w; i < clen; i += 8) {
        float v = 0.f;
#pragma unroll
        for (int k = 0; k < 8; k++) v += ctr[i * 256 + l + k * 32];
        v = warp_sum(v);
        if (l == 0) {
            const float lam = alph * (v * (1.0f / (float)NF)) + MU_C;
            const int gi = i0 + i;
            out[b * SEQ + gi] = lam;
            const float x0 = sx[i].x;
            out[NB * SEQ + b * (SEQ + 1) + gi] = (x0 > 0.f ? logf(lam) : 0.f) + LOGLIK2;
        }
    }
}

// ---------------- launch ----------------
extern "C" void kernel_launch(void* const* d_in, const int* in_sizes, int n_in,
                              void* d_out, int out_size)
{
    const float* X     = (const float*)d_in[0];
    const float* noise = (const float*)d_in[1];
    const float* W1    = (const float*)d_in[2];
    const float* b1    = (const float*)d_in[3];
    const float* W2    = (const float*)d_in[4];
    const float* b2    = (const float*)d_in[5];
    const float* Wm    = (const float*)d_in[6];
    const float* alpha = (const float*)d_in[7];
    float* out = (float*)d_out;

    mlp_womg<<<NF, 128>>>(noise, W1, b1, W2, b2, Wm);
    chunk_sums<<<NB * NCH, 256>>>(X);
    scan_sums<<<NB * 4, 128>>>(out);
    main_contract<<<NB * NCH, 256>>>(X, alpha, out);
}